// round 15
// baseline (speedup 1.0000x reference)
#include <cuda_runtime.h>
#include <math.h>

#define D     128
#define SEQ   200
#define BATCH 1024
#define NQV   50000
#define NCV   1000
#define NQD   101
#define NCD   101
#define RPC   8           // rows per CTA
#define NCTA  (BATCH / RPC)
#define NTHR  512         // 4 d-quarters x 128 output dims

typedef unsigned long long ull;

// ---------------- scratch (static device allocations only) ----------------
// 14 packed 128x128 weight blocks, layout pack[m][d4][j] = float4(W[j][4*d4 .. +3])
__device__ float4 g_pack[14 * 4096];            // 896 KB
__device__ float  g_EqP [NQV * D];              // Eq  @ WxA.T              (25.6 MB)
__device__ float  g_EcP [NCV * D];              // Ec  @ WxB.T
__device__ float  g_EqdP[NQD * D];              // Eqd @ WxC.T + bx
__device__ float  g_EcdP[NCD * D];              // Ecd @ WxD.T
__device__ float  g_CP1 [2 * D];                // Ecorr @ Wp1B.T + bp1
__device__ float  g_CP2 [2 * D];                // Ecorr @ Wp2B.T + bp2
__device__ float  g_Gc  [2 * D];                // Ecorr @ WkB.T  + bk
__device__ float  g_Gqd [NQD * D];              // Eqd   @ WkC.T
__device__ float  g_Gcd [NCD * D];              // Ecd   @ WkD.T

// ---------------- helpers ----------------
__device__ __forceinline__ float sigmoidf_(float x) {
    return __fdividef(1.0f, 1.0f + __expf(-x));
}
__device__ __forceinline__ float tanhf_(float x) {
    float t = __expf(-2.0f * fabsf(x));
    float r = __fdividef(1.0f - t, 1.0f + t);
    return copysignf(r, x);
}
__device__ __forceinline__ void fma2(ull &d, ull a, ull b) {
    asm("fma.rn.f32x2 %0, %1, %2, %0;" : "+l"(d) : "l"(a), "l"(b));
}
__device__ __forceinline__ float2 unpack2(ull v) {
    unsigned a, b;
    asm("mov.b64 {%0, %1}, %2;" : "=r"(a), "=r"(b) : "l"(v));
    return make_float2(__uint_as_float(a), __uint_as_float(b));
}

// ---------------- 1) weight packing ----------------
__global__ void pack_kernel(const float* __restrict__ Ws1, const float* __restrict__ Ws2,
                            const float* __restrict__ Wp1, const float* __restrict__ Wp2,
                            const float* __restrict__ Wk,  const float* __restrict__ Wx)
{
    const int m = blockIdx.x, d4 = blockIdx.y, j = threadIdx.x;
    const int srcsel[14] = {0,1,2,3,4, 5,5,5,5, 2,3, 4,4,4};
    const int strid [14] = {128,128,256,256,512, 512,512,512,512, 256,256, 512,512,512};
    const int offs  [14] = {0,0,0,0,0, 0,128,256,384, 128,128, 128,256,384};
    const float* srcs[6] = {Ws1, Ws2, Wp1, Wp2, Wk, Wx};
    const float* src = srcs[srcsel[m]];
    float4 v = *(const float4*)(src + (size_t)j * strid[m] + offs[m] + 4 * d4);
    g_pack[(m * 32 + d4) * 128 + j] = v;
}

// ---------------- 2) fused table projections (single launch) ----------------
// 9 jobs, each tiled in 16-row blocks. Block counts: {3125,63,7,7,1,1,1,7,7}.
#define PROJ_GRID 3219

__global__ void proj_all_kernel(const float* __restrict__ Eq,  const float* __restrict__ Ec,
                                const float* __restrict__ Eqd, const float* __restrict__ Ecd,
                                const float* __restrict__ Ecorr,
                                const float* __restrict__ bx,  const float* __restrict__ bp1,
                                const float* __restrict__ bp2, const float* __restrict__ bk)
{
    __shared__ __align__(16) float sE[16][D];
    const int j = threadIdx.x;

    // job decode
    int b = blockIdx.x, job = 0;
    const int nblk[9] = {3125, 63, 7, 7, 1, 1, 1, 7, 7};
    #pragma unroll
    for (int k = 0; k < 9; ++k) { if (b < nblk[k]) { job = k; break; } b -= nblk[k]; }

    const float* Es[9]   = {Eq, Ec, Eqd, Ecd, Ecorr, Ecorr, Ecorr, Eqd, Ecd};
    const int    nrows9[9] = {NQV, NCV, NQD, NCD, 2, 2, 2, NQD, NCD};
    const int    packI[9]  = {5, 6, 7, 8, 9, 10, 11, 12, 13};
    const float* bias9[9]  = {nullptr, nullptr, bx, nullptr, bp1, bp2, bk, nullptr, nullptr};
    float*       out9[9]   = {g_EqP, g_EcP, g_EqdP, g_EcdP, g_CP1, g_CP2, g_Gc, g_Gqd, g_Gcd};

    const float* E     = Es[job];
    const int    nrows = nrows9[job];
    const float* bias  = bias9[job];
    float*       out   = out9[job];

    const int i0 = b * 16;
    int nr = nrows - i0; if (nr > 16) nr = 16;

    for (int k = threadIdx.x; k < 16 * (D / 4); k += 128) {
        int i = k >> 5, c4 = k & 31;
        float4 v = (i < nr) ? *(const float4*)(E + (size_t)(i0 + i) * D + 4 * c4)
                            : make_float4(0.f, 0.f, 0.f, 0.f);
        *(float4*)&sE[i][4 * c4] = v;
    }
    __syncthreads();

    float bb = bias ? bias[j] : 0.0f;
    float acc[16];
    #pragma unroll
    for (int i = 0; i < 16; ++i) acc[i] = bb;

    const float4* __restrict__ W = g_pack + (size_t)packI[job] * 4096;
    #pragma unroll 4
    for (int d4 = 0; d4 < 32; ++d4) {
        const float4 w = W[d4 * 128 + j];
        #pragma unroll
        for (int i = 0; i < 16; ++i) {
            const float4 e = *(const float4*)&sE[i][4 * d4];
            acc[i] += w.x * e.x + w.y * e.y + w.z * e.z + w.w * e.w;
        }
    }
    for (int i = 0; i < nr; ++i) out[(size_t)(i0 + i) * D + j] = acc[i];
}

// ---------------- 3) persistent scan (d-pair f32x2) ----------------
// 512 threads = 4 d-quarters (q) x 128 output dims (j).
// Thread (q, j): owns rows {2q, 2q+1} at dim j; computes partial dots over
// d in [32q, 32q+32) for ALL 8 rows, f32x2-packed over ADJACENT d (no weight
// duplication: pack[d4][j] float4 = two natural d-pairs).
#define SMEM_SW_B   131072                   // Ws1+Ws2: 8192 float4
// act: 3*8*128 floats = 12KB ; red: 3*8*128*4 floats = 48KB ; idx+yred
#define SMEM_BYTES  (SMEM_SW_B + 12288 + 49152 + 256 + 128)

__global__ void __launch_bounds__(NTHR, 1)
scan_kernel(const int* __restrict__ qseq,  const int* __restrict__ cseq,
            const int* __restrict__ qdseq, const int* __restrict__ cdseq,
            const int* __restrict__ corrseq,
            const float* __restrict__ bs1, const float* __restrict__ bs2,
            const float* __restrict__ h0,  float* __restrict__ y)
{
    extern __shared__ __align__(16) unsigned char smem_raw[];
    float4* sW     = (float4*)smem_raw;                       // [0..8192) float4
    float*  s_sv   = (float*)(smem_raw + SMEM_SW_B);          // [8][128]
    float*  s_h    = s_sv  + 1024;                            // [8][128]
    float*  s_sdf  = s_h   + 1024;                            // [8][128]
    float*  s_red  = s_sdf + 1024;                            // [3][8][128][4]
    int*    s_idx  = (int*)(s_red + 12288);                   // [8][7]
    float*  s_yred = (float*)(s_idx + 64);                    // [16 warps][2]

    const int tid  = threadIdx.x;
    const int j    = tid & (D - 1);
    const int q    = tid >> 7;                 // d-quarter 0..3
    const int lane = tid & 31, warp = tid >> 5;
    const int rbase = blockIdx.x * RPC;
    const int r0   = 2 * q;                    // own rows r0, r0+1
    const int dd0  = q * 8;                    // d4 range [dd0, dd0+8)

    const float4*     __restrict__ sW1  = sW;                  // Ws1 (smem)
    const float4*     __restrict__ sW2  = sW + 4096;           // Ws2 (smem)
    const ulonglong2* __restrict__ gWk  = (const ulonglong2*)(g_pack + 4 * 4096);
    const ulonglong2* __restrict__ WP1  = (const ulonglong2*)(g_pack + 2 * 4096);
    const ulonglong2* __restrict__ WP2  = (const ulonglong2*)(g_pack + 3 * 4096);

    // stage Ws1, Ws2 into shared (once)
    for (int i = tid; i < 8192; i += NTHR) sW[i] = g_pack[i];

    const float bias1 = bs1[j], bias2 = bs2[j];

    // init own-row state (rows 2q, 2q+1)
    float h[2], x[2];
    #pragma unroll
    for (int rl = 0; rl < 2; ++rl) {
        const int b = rbase + r0 + rl;
        h[rl] = h0[(size_t)b * D + j];
        const int qi = qseq [b * SEQ], c  = cseq [b * SEQ];
        const int qd = qdseq[b * SEQ], cd = cdseq[b * SEQ];
        x[rl] = g_EqP[qi * D + j] + g_EcP[c * D + j] + g_EqdP[qd * D + j] + g_EcdP[cd * D + j];
    }
    if (tid < RPC) y[(size_t)(rbase + tid) * SEQ + (SEQ - 1)] = 0.0f;   // y[:, S-1]=0

    for (int t = 0; t < SEQ - 1; ++t) {
        // ---- (a) publish sv, h and this step's indices ----
        if (tid < RPC) {
            const int base = (rbase + tid) * SEQ + t;
            s_idx[tid * 7 + 0] = corrseq[base];
            s_idx[tid * 7 + 1] = qdseq [base];
            s_idx[tid * 7 + 2] = cdseq [base];
            s_idx[tid * 7 + 3] = qseq  [base + 1];
            s_idx[tid * 7 + 4] = cseq  [base + 1];
            s_idx[tid * 7 + 5] = qdseq [base + 1];
            s_idx[tid * 7 + 6] = cdseq [base + 1];
        }
        s_sv[(r0 + 0) * 128 + j] = x[0] - h[0];
        s_sv[(r0 + 1) * 128 + j] = x[1] - h[1];
        s_h [(r0 + 0) * 128 + j] = h[0];
        s_h [(r0 + 1) * 128 + j] = h[1];
        __syncthreads();                                         // #1

        // deferred y write for step t-1 (s_yred from prev iter, made visible by bar#1)
        if (tid < RPC && t > 0) {
            const int r = tid, qr = r >> 1, rl = r & 1;
            const float s = s_yred[(4 * qr + 0) * 2 + rl] + s_yred[(4 * qr + 1) * 2 + rl]
                          + s_yred[(4 * qr + 2) * 2 + rl] + s_yred[(4 * qr + 3) * 2 + rl];
            y[(size_t)(rbase + r) * SEQ + (t - 1)] = sigmoidf_(s);
        }

        // ---- (b) Phase A+C: a1=Ws1*sv, a2=Ws2*sv, c1=Wk*h over my d-quarter
        ull a1[8] = {0,0,0,0,0,0,0,0}, a2[8] = {0,0,0,0,0,0,0,0}, c1[8] = {0,0,0,0,0,0,0,0};
        ulonglong2 wkpf[2];
        wkpf[0] = gWk[(dd0 + 0) * 128 + j];
        wkpf[1] = gWk[(dd0 + 1) * 128 + j];
        #pragma unroll 4
        for (int dd = 0; dd < 8; ++dd) {
            const int d4 = dd0 + dd;
            const ulonglong2 w1 = *(const ulonglong2*)&sW1[d4 * 128 + j];   // d-pairs
            const ulonglong2 w2 = *(const ulonglong2*)&sW2[d4 * 128 + j];
            const ulonglong2 wk = wkpf[dd & 1];
            if (dd + 2 < 8) wkpf[dd & 1] = gWk[(d4 + 2) * 128 + j];
            #pragma unroll
            for (int r = 0; r < 8; ++r) {
                const ulonglong2 sv = *(const ulonglong2*)&s_sv[r * 128 + 4 * d4];
                const ulonglong2 hh = *(const ulonglong2*)&s_h [r * 128 + 4 * d4];
                fma2(a1[r], w1.x, sv.x); fma2(a1[r], w1.y, sv.y);
                fma2(a2[r], w2.x, sv.x); fma2(a2[r], w2.y, sv.y);
                fma2(c1[r], wk.x, hh.x); fma2(c1[r], wk.y, hh.y);
            }
        }
        // horizontal add + publish: s_red[((m*8 + r)*128 + j)*4 + q]
        #pragma unroll
        for (int r = 0; r < 8; ++r) {
            const float2 v1 = unpack2(a1[r]);
            const float2 v2 = unpack2(a2[r]);
            const float2 vc = unpack2(c1[r]);
            s_red[((0 * 8 + r) * 128 + j) * 4 + q] = v1.x + v1.y;
            s_red[((1 * 8 + r) * 128 + j) * 4 + q] = v2.x + v2.y;
            s_red[((2 * 8 + r) * 128 + j) * 4 + q] = vc.x + vc.y;
        }
        // gathers needed at (c): gate tables (L1/L2-hot, small)
        float gG[2];
        #pragma unroll
        for (int rl = 0; rl < 2; ++rl) {
            const int r = r0 + rl;
            const int ci = s_idx[r * 7 + 0], qd = s_idx[r * 7 + 1], cd = s_idx[r * 7 + 2];
            gG[rl] = g_Gc[ci * D + j] + g_Gqd[qd * D + j] + g_Gcd[cd * D + j];
        }
        __syncthreads();                                         // #2

        // x_{t+1} gathers (EqP is L2-resident; consumed at (e), ~2 phases later)
        float gx[2][4];
        #pragma unroll
        for (int rl = 0; rl < 2; ++rl) {
            const int r = r0 + rl;
            const int q2  = s_idx[r * 7 + 3], c2  = s_idx[r * 7 + 4];
            const int qd2 = s_idx[r * 7 + 5], cd2 = s_idx[r * 7 + 6];
            gx[rl][0] = g_EqP [q2  * D + j];
            gx[rl][1] = g_EcP [c2  * D + j];
            gx[rl][2] = g_EqdP[qd2 * D + j];
            gx[rl][3] = g_EcdP[cd2 * D + j];
        }

        // ---- (c) combine own rows -> sdf (smem), g (regs) ----
        float g[2];
        #pragma unroll
        for (int rl = 0; rl < 2; ++rl) {
            const int r = r0 + rl;
            const float4 va1 = *(const float4*)&s_red[((0 * 8 + r) * 128 + j) * 4];
            const float4 va2 = *(const float4*)&s_red[((1 * 8 + r) * 128 + j) * 4];
            const float4 vc  = *(const float4*)&s_red[((2 * 8 + r) * 128 + j) * 4];
            const float A1 = (va1.x + va1.y) + (va1.z + va1.w) + bias1;
            const float A2 = (va2.x + va2.y) + (va2.z + va2.w) + bias2;
            const float C1 = (vc.x  + vc.y)  + (vc.z  + vc.w)  + gG[rl];
            s_sdf[r * 128 + j] = sigmoidf_(A1) * tanhf_(A2);
            g[rl] = sigmoidf_(C1);
        }
        __syncthreads();                                         // #3

        // pka bias gathers (consumed at (e))
        float cp1v[2], cp2v[2];
        #pragma unroll
        for (int rl = 0; rl < 2; ++rl) {
            const int ci = s_idx[(r0 + rl) * 7 + 0];
            cp1v[rl] = g_CP1[ci * D + j];
            cp2v[rl] = g_CP2[ci * D + j];
        }

        // ---- (d) Phase B: b1=Wp1*sdf, b2=Wp2*sdf (streamed, 2-deep prefetch)
        ull b1[8] = {0,0,0,0,0,0,0,0}, b2[8] = {0,0,0,0,0,0,0,0};
        ulonglong2 f1[2], f2[2];
        f1[0] = WP1[(dd0 + 0) * 128 + j];  f2[0] = WP2[(dd0 + 0) * 128 + j];
        f1[1] = WP1[(dd0 + 1) * 128 + j];  f2[1] = WP2[(dd0 + 1) * 128 + j];
        #pragma unroll 4
        for (int dd = 0; dd < 8; ++dd) {
            const int d4 = dd0 + dd;
            const ulonglong2 w1 = f1[dd & 1], w2 = f2[dd & 1];
            if (dd + 2 < 8) {
                f1[dd & 1] = WP1[(d4 + 2) * 128 + j];
                f2[dd & 1] = WP2[(d4 + 2) * 128 + j];
            }
            #pragma unroll
            for (int r = 0; r < 8; ++r) {
                const ulonglong2 sd = *(const ulonglong2*)&s_sdf[r * 128 + 4 * d4];
                fma2(b1[r], w1.x, sd.x); fma2(b1[r], w1.y, sd.y);
                fma2(b2[r], w2.x, sd.x); fma2(b2[r], w2.y, sd.y);
            }
        }
        #pragma unroll
        for (int r = 0; r < 8; ++r) {
            const float2 v1 = unpack2(b1[r]);
            const float2 v2 = unpack2(b2[r]);
            s_red[((0 * 8 + r) * 128 + j) * 4 + q] = v1.x + v1.y;
            s_red[((1 * 8 + r) * 128 + j) * 4 + q] = v2.x + v2.y;
        }
        __syncthreads();                                         // #4

        // ---- (e) combine -> pka -> h update; x_{t+1}; y dot (write deferred) ----
        #pragma unroll
        for (int rl = 0; rl < 2; ++rl) {
            const int r = r0 + rl;
            const float4 vb1 = *(const float4*)&s_red[((0 * 8 + r) * 128 + j) * 4];
            const float4 vb2 = *(const float4*)&s_red[((1 * 8 + r) * 128 + j) * 4];
            const float B1 = (vb1.x + vb1.y) + (vb1.z + vb1.w) + cp1v[rl];
            const float B2 = (vb2.x + vb2.y) + (vb2.z + vb2.w) + cp2v[rl];
            const float pka = sigmoidf_(B1) * tanhf_(B2);
            h[rl] = g[rl] * h[rl] + (1.0f - g[rl]) * pka;
        }
        #pragma unroll
        for (int rl = 0; rl < 2; ++rl) {
            x[rl] = (gx[rl][0] + gx[rl][1]) + (gx[rl][2] + gx[rl][3]);   // x_{t+1}
            float v = x[rl] * h[rl];
            v += __shfl_xor_sync(0xffffffffu, v, 16);
            v += __shfl_xor_sync(0xffffffffu, v, 8);
            v += __shfl_xor_sync(0xffffffffu, v, 4);
            v += __shfl_xor_sync(0xffffffffu, v, 2);
            v += __shfl_xor_sync(0xffffffffu, v, 1);
            if (lane == 0) s_yred[warp * 2 + rl] = v;
        }
        // no barrier: next iteration's bar#1 publishes s_yred before the y write
    }

    __syncthreads();
    if (tid < RPC) {
        const int r = tid, qr = r >> 1, rl = r & 1;
        const float s = s_yred[(4 * qr + 0) * 2 + rl] + s_yred[(4 * qr + 1) * 2 + rl]
                      + s_yred[(4 * qr + 2) * 2 + rl] + s_yred[(4 * qr + 3) * 2 + rl];
        y[(size_t)(rbase + r) * SEQ + (SEQ - 2)] = sigmoidf_(s);
    }
}

// ---------------- launch ----------------
extern "C" void kernel_launch(void* const* d_in, const int* in_sizes, int n_in,
                              void* d_out, int out_size)
{
    const int*   qseq    = (const int*)  d_in[0];
    const int*   cseq    = (const int*)  d_in[1];
    const int*   qdseq   = (const int*)  d_in[2];
    const int*   cdseq   = (const int*)  d_in[3];
    const int*   corrseq = (const int*)  d_in[4];
    const float* Eq      = (const float*)d_in[5];
    const float* Ec      = (const float*)d_in[6];
    const float* Eqd     = (const float*)d_in[7];
    const float* Ecd     = (const float*)d_in[8];
    const float* Ecorr   = (const float*)d_in[9];
    const float* Wx      = (const float*)d_in[10];
    const float* bx      = (const float*)d_in[11];
    const float* Ws1     = (const float*)d_in[12];
    const float* bs1     = (const float*)d_in[13];
    const float* Ws2     = (const float*)d_in[14];
    const float* bs2     = (const float*)d_in[15];
    const float* Wp1     = (const float*)d_in[16];
    const float* bp1     = (const float*)d_in[17];
    const float* Wp2     = (const float*)d_in[18];
    const float* bp2     = (const float*)d_in[19];
    const float* Wk      = (const float*)d_in[20];
    const float* bk      = (const float*)d_in[21];
    const float* h0      = (const float*)d_in[22];
    float* y = (float*)d_out;

    static int smem_set = 0;
    if (!smem_set) {
        cudaFuncSetAttribute(scan_kernel, cudaFuncAttributeMaxDynamicSharedMemorySize,
                             SMEM_BYTES);
        smem_set = 1;
    }

    // 1) pack all 128x128 weight blocks into [d4][j] float4 layout
    pack_kernel<<<dim3(14, 32), 128>>>(Ws1, Ws2, Wp1, Wp2, Wk, Wx);

    // 2) fold embedding tables through their weight blocks (single fused launch)
    proj_all_kernel<<<PROJ_GRID, 128>>>(Eq, Ec, Eqd, Ecd, Ecorr, bx, bp1, bp2, bk);

    // 3) persistent recurrent scan (rows independent -> no inter-CTA sync)
    scan_kernel<<<NCTA, NTHR, SMEM_BYTES>>>(qseq, cseq, qdseq, cdseq, corrseq,
                                            bs1, bs2, h0, y);
}